// round 7
// baseline (speedup 1.0000x reference)
#include <cuda_runtime.h>

#define HW (512 * 512)
#define EPS 1e-6f

// 16 MB static scratch: 4 neighbor planes repacked as weight-premultiplied,
// 16B-aligned float4. Static __device__ array => no allocation, graph-safe.
__device__ float4 g_planes[4 * HW];

// ---------------- Kernel 1: repack + premultiply ----------------
// One thread per (neighbor, point): reads the 12B triple from `data`,
// writes w[n] * (r,g,b) as an aligned float4 into g_planes.
__global__ __launch_bounds__(256) void repack_kernel(
    const float* __restrict__ data,      // (9,9,512,512,3)
    const float* __restrict__ cam_xyz,   // (3,)
    const int*   __restrict__ neighbors) // (4,2)
{
    const int tid = blockIdx.x * blockDim.x + threadIdx.x;  // 0 .. 4*HW-1
    const int n   = tid >> 18;         // HW = 2^18
    const int p   = tid & (HW - 1);

    // ---- weights (all loads L1-broadcast) ----
    const float c0 = __ldg(cam_xyz + 0);
    const float c1 = __ldg(cam_xyz + 1);

    int n0[4], n1[4];
    float t[4];
#pragma unroll
    for (int j = 0; j < 4; j++) {
        n0[j] = __ldg(neighbors + 2 * j + 0);
        n1[j] = __ldg(neighbors + 2 * j + 1);
        const float d0 = c0 - (float)n0[j];
        const float d1 = c1 - (float)n1[j];
        float v = fabsf(d0 * d1);
        t[j] = (v <= EPS) ? 0.0f : v;   // threshold BEFORE sum (matches ref)
    }
    const float s = t[0] + t[1] + t[2] + t[3];
    // flip: weight paired with gathered[n] comes from t of neighbor (3-n)
    const float x  = t[3 - n] / s;
    const float wn = (fabsf(x) <= EPS) ? 0.0f : x;

    // ---- stream-copy this neighbor's plane, premultiplied ----
    // base float index < 81*512*512*3 = 63.7M: fits int32
    const int base = (n0[n] * 9 + n1[n]) * (HW * 3) + p * 3;
    const float r = __ldg(data + base + 0);
    const float g = __ldg(data + base + 1);
    const float b = __ldg(data + base + 2);
    g_planes[tid] = make_float4(wn * r, wn * g, wn * b, 0.0f);
}

// ---------------- Kernel 2: pure gather-sum ----------------
__global__ __launch_bounds__(128) void Interpolate_28664611734214_kernel(
    const int2* __restrict__ uv,   // (4,512,512,2) as int2
    float*      __restrict__ out)  // flat (HW,3) == reshape(3,H,W)
{
    const int pix = blockIdx.x * blockDim.x + threadIdx.x;  // grid tiles HW exactly

    float r = 0.f, g = 0.f, b = 0.f;
#pragma unroll
    for (int n = 0; n < 4; n++) {
        const int2 q = __ldg(uv + n * HW + pix);            // (u, v)
        const float4 A = __ldg(&g_planes[n * HW + (q.x << 9) + q.y]);  // 1 aligned LDG.128
        r += A.x; g += A.y; b += A.z;
    }

    // einsum result is (HW,3) then reinterpreted as (3,H,W): interleaved layout
    out[3 * pix + 0] = r;
    out[3 * pix + 1] = g;
    out[3 * pix + 2] = b;
}

extern "C" void kernel_launch(void* const* d_in, const int* in_sizes, int n_in,
                              void* d_out, int out_size) {
    // metadata order: data, pixel, cam_xyz, neighbors, uv
    const float* data      = (const float*)d_in[0];
    // d_in[1] = pixel, only its shape is used by the reference -> unused here
    const float* cam_xyz   = (const float*)d_in[2];
    const int*   neighbors = (const int*)d_in[3];
    const int2*  uv        = (const int2*)d_in[4];
    float*       out       = (float*)d_out;

    // Kernel 1: repack the 4 touched planes (same stream => ordered in graph)
    repack_kernel<<<(4 * HW) / 256, 256>>>(data, cam_xyz, neighbors);

    // Kernel 2: gather + sum
    Interpolate_28664611734214_kernel<<<HW / 128, 128>>>(uv, out);
}

// round 8
// speedup vs baseline: 1.1555x; 1.1555x over previous
#include <cuda_runtime.h>
#include <cuda_fp16.h>

#define HW (512 * 512)
#define EPS 1e-6f

// 8 MB static scratch: 4 neighbor planes as weight-premultiplied half4
// (r,g,b,0 in fp16 = 8 bytes = one uint2 per point). Alloc-free, graph-safe.
__device__ uint2 g_ph[4 * HW];

__device__ __forceinline__ float plane_weight(
    const float* __restrict__ cam_xyz,
    const int*   __restrict__ neighbors,
    int n, int* pn0, int* pn1)
{
    const float c0 = __ldg(cam_xyz + 0);
    const float c1 = __ldg(cam_xyz + 1);
    int   n0[4], n1[4];
    float t[4];
#pragma unroll
    for (int j = 0; j < 4; j++) {
        n0[j] = __ldg(neighbors + 2 * j + 0);
        n1[j] = __ldg(neighbors + 2 * j + 1);
        const float d0 = c0 - (float)n0[j];
        const float d1 = c1 - (float)n1[j];
        float v = fabsf(d0 * d1);
        t[j] = (v <= EPS) ? 0.0f : v;          // threshold BEFORE sum
    }
    const float s = t[0] + t[1] + t[2] + t[3];
    const float x = t[3 - n] / s;              // flip pairing
    *pn0 = n0[n]; *pn1 = n1[n];
    return (fabsf(x) <= EPS) ? 0.0f : x;
}

// ---------------- Kernel 1: vectorized repack + premultiply + fp16 ----------
// One thread per 4 points of one plane: 3x LDG.128 in, 2x STG.128 out.
__global__ __launch_bounds__(256) void repack_kernel(
    const float4* __restrict__ data4,    // (9,9,512,512,3) as float4 chunks
    const float*  __restrict__ cam_xyz,
    const int*    __restrict__ neighbors)
{
    const int tid = blockIdx.x * blockDim.x + threadIdx.x;  // 0 .. HW-1
    const int n   = tid >> 16;            // plane (HW/4 = 65536 groups/plane)
    const int g   = tid & 65535;          // group of 4 points

    int n0, n1;
    const float wn = plane_weight(cam_xyz, neighbors, n, &n0, &n1);

    // source: 12 consecutive floats = 3 aligned float4 chunks
    // chunk base: (n0*9+n1)*(HW*3/4) + 3*g   (HW*3/4 = 196608)
    const int c0 = (n0 * 9 + n1) * 196608 + 3 * g;
    const float4 A = __ldg(data4 + c0 + 0);   // p0.r p0.g p0.b p1.r
    const float4 B = __ldg(data4 + c0 + 1);   // p1.g p1.b p2.r p2.g
    const float4 C = __ldg(data4 + c0 + 2);   // p2.b p3.r p3.g p3.b

    __half2 h[8];
    h[0] = __floats2half2_rn(wn * A.x, wn * A.y);   // p0 r,g
    h[1] = __floats2half2_rn(wn * A.z, 0.0f);       // p0 b
    h[2] = __floats2half2_rn(wn * A.w, wn * B.x);   // p1 r,g
    h[3] = __floats2half2_rn(wn * B.y, 0.0f);       // p1 b
    h[4] = __floats2half2_rn(wn * B.z, wn * B.w);   // p2 r,g
    h[5] = __floats2half2_rn(wn * C.x, 0.0f);       // p2 b
    h[6] = __floats2half2_rn(wn * C.y, wn * C.z);   // p3 r,g
    h[7] = __floats2half2_rn(wn * C.w, 0.0f);       // p3 b

    // dst: 4 consecutive uint2 = 32B = 2 aligned uint4 stores
    uint4* dst = reinterpret_cast<uint4*>(&g_ph[(n << 18) + (g << 2)]);
    const unsigned* u = reinterpret_cast<const unsigned*>(h);
    dst[0] = make_uint4(u[0], u[1], u[2], u[3]);
    dst[1] = make_uint4(u[4], u[5], u[6], u[7]);
}

// ---------------- Kernel 2: LDG.64 gather-sum ----------------
__global__ __launch_bounds__(256) void Interpolate_28664611734214_kernel(
    const int2* __restrict__ uv,   // (4,512,512,2) as int2
    float*      __restrict__ out)  // flat (HW,3) == reshape(3,H,W)
{
    const int pix = blockIdx.x * blockDim.x + threadIdx.x;  // grid tiles HW

    float r = 0.f, g = 0.f, b = 0.f;
#pragma unroll
    for (int n = 0; n < 4; n++) {
        const int2 q = __ldg(uv + n * HW + pix);                 // (u, v)
        const uint2 raw = __ldg(&g_ph[(n << 18) + (q.x << 9) + q.y]);  // LDG.64
        const __half2 rg = *reinterpret_cast<const __half2*>(&raw.x);
        const __half2 bp = *reinterpret_cast<const __half2*>(&raw.y);
        const float2 frg = __half22float2(rg);
        r += frg.x;
        g += frg.y;
        b += __low2float(bp);
    }

    // einsum result is (HW,3) then reinterpreted as (3,H,W): interleaved
    out[3 * pix + 0] = r;
    out[3 * pix + 1] = g;
    out[3 * pix + 2] = b;
}

extern "C" void kernel_launch(void* const* d_in, const int* in_sizes, int n_in,
                              void* d_out, int out_size) {
    // metadata order: data, pixel, cam_xyz, neighbors, uv
    const float4* data4     = (const float4*)d_in[0];
    // d_in[1] = pixel, only its shape is used by the reference -> unused here
    const float*  cam_xyz   = (const float*)d_in[2];
    const int*    neighbors = (const int*)d_in[3];
    const int2*   uv        = (const int2*)d_in[4];
    float*        out       = (float*)d_out;

    // Kernel 1: repack 4 planes -> premultiplied fp16 (same stream => ordered)
    repack_kernel<<<HW / 256, 256>>>(data4, cam_xyz, neighbors);

    // Kernel 2: gather + sum
    Interpolate_28664611734214_kernel<<<HW / 256, 256>>>(uv, out);
}

// round 9
// speedup vs baseline: 1.3145x; 1.1376x over previous
#include <cuda_runtime.h>

#define HW (512 * 512)
#define EPS 1e-6f

// Divergent 16B gather split into 4 lane-quarter predicated loads.
// Same dest regs, disjoint predicates: every lane written exactly once.
// Non-volatile asm (pure load) so ptxas keeps scheduling freedom.
__device__ __forceinline__ float4 ldg128_q(const float4* p, int grp) {
    float4 A;
    asm("{\n\t"
        ".reg .pred q0,q1,q2,q3;\n\t"
        "setp.eq.s32 q0, %4, 0;\n\t"
        "setp.eq.s32 q1, %4, 1;\n\t"
        "setp.eq.s32 q2, %4, 2;\n\t"
        "setp.eq.s32 q3, %4, 3;\n\t"
        "@q0 ld.global.nc.v4.f32 {%0,%1,%2,%3}, [%5];\n\t"
        "@q1 ld.global.nc.v4.f32 {%0,%1,%2,%3}, [%5];\n\t"
        "@q2 ld.global.nc.v4.f32 {%0,%1,%2,%3}, [%5];\n\t"
        "@q3 ld.global.nc.v4.f32 {%0,%1,%2,%3}, [%5];\n\t"
        "}"
        : "=f"(A.x), "=f"(A.y), "=f"(A.z), "=f"(A.w)
        : "r"(grp), "l"(p));
    return A;
}

// Second-chunk 8B load: quarter-split AND gated on (o >= 2).
__device__ __forceinline__ float2 ldg64_q_pred(const float2* p, int grp, int o) {
    float2 B;
    asm("{\n\t"
        ".reg .pred t,q0,q1,q2,q3;\n\t"
        "setp.ge.s32 t, %3, 2;\n\t"
        "setp.eq.and.s32 q0, %2, 0, t;\n\t"
        "setp.eq.and.s32 q1, %2, 1, t;\n\t"
        "setp.eq.and.s32 q2, %2, 2, t;\n\t"
        "setp.eq.and.s32 q3, %2, 3, t;\n\t"
        "@q0 ld.global.nc.v2.f32 {%0,%1}, [%4];\n\t"
        "@q1 ld.global.nc.v2.f32 {%0,%1}, [%4];\n\t"
        "@q2 ld.global.nc.v2.f32 {%0,%1}, [%4];\n\t"
        "@q3 ld.global.nc.v2.f32 {%0,%1}, [%4];\n\t"
        "}"
        : "=f"(B.x), "=f"(B.y)
        : "r"(grp), "r"(o), "l"(p));
    return B;
}

__global__ __launch_bounds__(128) void Interpolate_28664611734214_kernel(
    const float4* __restrict__ data4,    // (9,9,512,512,3) viewed as float4 chunks
    const float*  __restrict__ cam_xyz,  // (3,)
    const int*    __restrict__ neighbors,// (4,2)
    const int2*   __restrict__ uv,       // (4,512,512,2) as int2
    float*        __restrict__ out)      // flat (HW,3) == reshape(3,H,W)
{
    const int pix = blockIdx.x * blockDim.x + threadIdx.x;   // grid tiles HW
    const int grp = (threadIdx.x & 31) >> 3;                 // lane quarter

    // ---- head of the critical path: issue all 4 uv loads first ----
    int2 q[4];
#pragma unroll
    for (int n = 0; n < 4; n++)
        q[n] = __ldg(uv + n * HW + pix);

    // ---- weights (tiny; all loads L1-broadcast; fills the uv-load shadow) ----
    const float c0 = __ldg(cam_xyz + 0);
    const float c1 = __ldg(cam_xyz + 1);

    int n0[4], n1[4];
    float t[4];
#pragma unroll
    for (int j = 0; j < 4; j++) {
        n0[j] = __ldg(neighbors + 2 * j + 0);
        n1[j] = __ldg(neighbors + 2 * j + 1);
        const float d0 = c0 - (float)n0[j];
        const float d1 = c1 - (float)n1[j];
        float v = fabsf(d0 * d1);
        t[j] = (v <= EPS) ? 0.0f : v;   // threshold BEFORE sum (matches ref)
    }
    const float s = t[0] + t[1] + t[2] + t[3];

    float w[4];
#pragma unroll
    for (int n = 0; n < 4; n++) {
        // flip: weight for gathered[n] pairs with t of neighbor (3-n)
        const float x = t[3 - n] / s;
        w[n] = (fabsf(x) <= EPS) ? 0.0f : x;
    }

    // ---- gather + weighted sum ----
    float r = 0.f, g = 0.f, b = 0.f;
#pragma unroll
    for (int n = 0; n < 4; n++) {
        // float index of R channel: f = 3 * point_idx  (< 64M, fits int32)
        const int f     = (((n0[n] * 9 + n1[n]) * 512 + q[n].x) * 512 + q[n].y) * 3;
        const int chunk = f >> 2;       // float4 index
        const int o     = f & 3;        // offset within chunk

        const float4 A = ldg128_q(data4 + chunk, grp);
        const float2 B = ldg64_q_pred((const float2*)(data4 + chunk + 1), grp, o);

        float rr, gg, bb;
        if (o == 0)      { rr = A.x; gg = A.y; bb = A.z; }
        else if (o == 1) { rr = A.y; gg = A.z; bb = A.w; }
        else if (o == 2) { rr = A.z; gg = A.w; bb = B.x; }
        else             { rr = A.w; gg = B.x; bb = B.y; }

        const float wn = w[n];
        r += wn * rr;
        g += wn * gg;
        b += wn * bb;
    }

    // einsum result is (HW,3) then reinterpreted as (3,H,W): interleaved layout
    out[3 * pix + 0] = r;
    out[3 * pix + 1] = g;
    out[3 * pix + 2] = b;
}

extern "C" void kernel_launch(void* const* d_in, const int* in_sizes, int n_in,
                              void* d_out, int out_size) {
    // metadata order: data, pixel, cam_xyz, neighbors, uv
    const float4* data4     = (const float4*)d_in[0];
    // d_in[1] = pixel, only its shape is used by the reference -> unused here
    const float*  cam_xyz   = (const float*)d_in[2];
    const int*    neighbors = (const int*)d_in[3];
    const int2*   uv        = (const int2*)d_in[4];
    float*        out       = (float*)d_out;

    const int threads = 128;
    const int blocks  = HW / threads;   // 2048, tiles HW exactly
    Interpolate_28664611734214_kernel<<<blocks, threads>>>(
        data4, cam_xyz, neighbors, uv, out);
}